// round 8
// baseline (speedup 1.0000x reference)
#include <cuda_runtime.h>
#include <math.h>

#define NN    50000
#define EE    800000
#define ET    (EE + NN)
#define HC    128
#define H4    4
#define EPSI  1e-5f
#define SKIPC 0.5f
#define NEGS  0.2f
#define SCAN_BLOCKS ((NN + 255) / 256)   // 196
#define BNSLOTS 32
#define WSTRIDE 132                       // smem row stride (floats): 132 % 32 == 4

// ---------------- static device scratch (no allocations allowed) ----------------
__device__ int   g_is64;
__device__ int   g_count[NN];
__device__ int   g_rowptr[NN + 1];
__device__ int   g_cursor[NN];
__device__ int   g_col[ET];
__device__ int   g_part[SCAN_BLOCKS];
__device__ int   g_partoff[SCAN_BLOCKS];
__device__ __align__(16) float g_bufA[NN * HC];
__device__ __align__(16) float g_bufB[NN * HC];
__device__ __align__(16) float g_bufC[NN * HC];
__device__ __align__(16) float g_als[NN * H4];
__device__ __align__(16) float g_ald[NN * H4];
__device__ float g_bnpsum[2 * BNSLOTS * HC];
__device__ float g_bnpsq[2 * BNSLOTS * HC];
__device__ float g_scale[2 * HC];
__device__ float g_shift[2 * HC];

// edge_index may be int32 or int64 (jax x64 flag dependent). Detect on device.
__global__ void detect_kernel(const int* __restrict__ ei32) {
    __shared__ int any;
    int t = threadIdx.x;
    if (t == 0) any = 0;
    __syncthreads();
    if (ei32[2 * t + 1] != 0) atomicOr(&any, 1);
    __syncthreads();
    if (t == 0) g_is64 = any ? 0 : 1;
}

__device__ __forceinline__ int ld_edge(const int* __restrict__ ei32, int pos) {
    return g_is64 ? ei32[2 * pos] : ei32[pos];
}

// ---------------- CSR construction ----------------
__global__ void init_kernel() {
    int i = blockIdx.x * blockDim.x + threadIdx.x;
    if (i < NN) g_count[i] = 1;               // self-loop pre-counted
    if (i < 2 * BNSLOTS * HC) { g_bnpsum[i] = 0.f; g_bnpsq[i] = 0.f; }
}

__global__ void hist_kernel(const int* __restrict__ ei32) {
    int e = blockIdx.x * blockDim.x + threadIdx.x;
    if (e < EE) {
        int d = ld_edge(ei32, EE + e);
        if ((unsigned)d < NN) atomicAdd(&g_count[d], 1);
    }
}

__global__ void scanA_kernel() {            // per-block sums
    __shared__ int sm[256];
    int t = threadIdx.x;
    int idx = blockIdx.x * 256 + t;
    sm[t] = (idx < NN) ? g_count[idx] : 0;
    __syncthreads();
    for (int o = 128; o; o >>= 1) {
        if (t < o) sm[t] += sm[t + o];
        __syncthreads();
    }
    if (t == 0) g_part[blockIdx.x] = sm[0];
}

__global__ void scanB_kernel() {            // exclusive scan of block sums
    __shared__ int sm[256];
    int t = threadIdx.x;
    sm[t] = (t < SCAN_BLOCKS) ? g_part[t] : 0;
    __syncthreads();
    for (int o = 1; o < 256; o <<= 1) {
        int v = (t >= o) ? sm[t - o] : 0;
        __syncthreads();
        sm[t] += v;
        __syncthreads();
    }
    if (t < SCAN_BLOCKS) g_partoff[t] = (t > 0) ? sm[t - 1] : 0;
}

__global__ void scanC_kernel() {            // in-block inclusive scan + offset
    __shared__ int sm[256];
    int t = threadIdx.x;
    int idx = blockIdx.x * 256 + t;
    int v = (idx < NN) ? g_count[idx] : 0;
    sm[t] = v;
    __syncthreads();
    for (int o = 1; o < 256; o <<= 1) {
        int u = (t >= o) ? sm[t - o] : 0;
        __syncthreads();
        sm[t] += u;
        __syncthreads();
    }
    if (idx < NN) g_rowptr[idx + 1] = g_partoff[blockIdx.x] + sm[t];
    if (idx == 0) g_rowptr[0] = 0;
}

__global__ void selfloop_kernel() {
    int n = blockIdx.x * blockDim.x + threadIdx.x;
    if (n < NN) {
        int p = g_rowptr[n];
        g_col[p] = n;                          // self-loop first
        g_cursor[n] = p + 1;
    }
}

__global__ void scatter_kernel(const int* __restrict__ ei32) {
    int e = blockIdx.x * blockDim.x + threadIdx.x;
    if (e < EE) {
        int s = ld_edge(ei32, e);
        int d = ld_edge(ei32, EE + e);
        if ((unsigned)d < NN && (unsigned)s < NN) {
            int pos = atomicAdd(&g_cursor[d], 1);
            g_col[pos] = s;
        }
    }
}

// ------------- 128-col GEMM: W resident in SMEM, X via LDG broadcast ------------
// Block: 256 threads, 64 rows. Thread (tx,ty): rows ty+8i, cols tx+32j (j = head).
// No barriers in the mainloop. XFORM: 0 = none, 1 = v -> relu(bn0(v))
template <int XFORM>
__global__ void gemm128_kernel(const float* __restrict__ X, const float* __restrict__ W,
                               float* __restrict__ Y,
                               const float* __restrict__ a_s, const float* __restrict__ a_d,
                               int nrows) {
    extern __shared__ float Ws[];    // [128][WSTRIDE]
    int t  = threadIdx.x;
    int tx = t & 31, ty = t >> 5;
    int row0 = blockIdx.x * 64;

    // Load full W (128x128) into smem: coalesced LDG.128 + contiguous STS.128
    for (int i = t; i < 128 * 32; i += 256) {
        int c = i >> 5, kg = i & 31;
        *(float4*)&Ws[c * WSTRIDE + 4 * kg] = *(const float4*)&W[c * 128 + 4 * kg];
    }
    __syncthreads();

    float acc[8][4];
#pragma unroll
    for (int i = 0; i < 8; i++)
#pragma unroll
        for (int j = 0; j < 4; j++) acc[i][j] = 0.f;

    bool full = (row0 + 64 <= nrows);
    if (full) {
        const float* xp = X + (row0 + ty) * 128;
#pragma unroll 4
        for (int kg = 0; kg < 32; kg++) {
            float4 xv[8];
#pragma unroll
            for (int i = 0; i < 8; i++) {
                float4 v = *(const float4*)(xp + i * 8 * 128 + 4 * kg);
                if (XFORM == 1) {
                    int c = 4 * kg;
                    v.x = fmaxf(fmaf(v.x, g_scale[c],     g_shift[c]),     0.f);
                    v.y = fmaxf(fmaf(v.y, g_scale[c + 1], g_shift[c + 1]), 0.f);
                    v.z = fmaxf(fmaf(v.z, g_scale[c + 2], g_shift[c + 2]), 0.f);
                    v.w = fmaxf(fmaf(v.w, g_scale[c + 3], g_shift[c + 3]), 0.f);
                }
                xv[i] = v;
            }
            float4 wv[4];
#pragma unroll
            for (int j = 0; j < 4; j++)
                wv[j] = *(const float4*)&Ws[(tx + 32 * j) * WSTRIDE + 4 * kg];
#pragma unroll
            for (int i = 0; i < 8; i++)
#pragma unroll
                for (int j = 0; j < 4; j++)
                    acc[i][j] += xv[i].x * wv[j].x + xv[i].y * wv[j].y +
                                 xv[i].z * wv[j].z + xv[i].w * wv[j].w;
        }
    } else {
        for (int kg = 0; kg < 32; kg++) {
            float4 xv[8];
#pragma unroll
            for (int i = 0; i < 8; i++) {
                int row = row0 + ty + 8 * i;
                float4 v = make_float4(0.f, 0.f, 0.f, 0.f);
                if (row < nrows) {
                    v = *(const float4*)&X[row * 128 + 4 * kg];
                    if (XFORM == 1) {
                        int c = 4 * kg;
                        v.x = fmaxf(fmaf(v.x, g_scale[c],     g_shift[c]),     0.f);
                        v.y = fmaxf(fmaf(v.y, g_scale[c + 1], g_shift[c + 1]), 0.f);
                        v.z = fmaxf(fmaf(v.z, g_scale[c + 2], g_shift[c + 2]), 0.f);
                        v.w = fmaxf(fmaf(v.w, g_scale[c + 3], g_shift[c + 3]), 0.f);
                    }
                }
                xv[i] = v;
            }
            float4 wv[4];
#pragma unroll
            for (int j = 0; j < 4; j++)
                wv[j] = *(const float4*)&Ws[(tx + 32 * j) * WSTRIDE + 4 * kg];
#pragma unroll
            for (int i = 0; i < 8; i++)
#pragma unroll
                for (int j = 0; j < 4; j++)
                    acc[i][j] += xv[i].x * wv[j].x + xv[i].y * wv[j].y +
                                 xv[i].z * wv[j].z + xv[i].w * wv[j].w;
        }
    }

    // store + fused 4-head attention-logit epilogue (head j == accumulator j)
    float asr[4], adr[4];
#pragma unroll
    for (int j = 0; j < 4; j++) {
        asr[j] = a_s[j * 32 + tx];
        adr[j] = a_d[j * 32 + tx];
    }
#pragma unroll
    for (int i = 0; i < 8; i++) {
        int row = row0 + ty + 8 * i;
        if (row < nrows) {
#pragma unroll
            for (int j = 0; j < 4; j++) {
                Y[row * 128 + tx + 32 * j] = acc[i][j];
                float ss = acc[i][j] * asr[j];
                float dd = acc[i][j] * adr[j];
#pragma unroll
                for (int o = 16; o; o >>= 1) {
                    ss += __shfl_xor_sync(0xffffffffu, ss, o);
                    dd += __shfl_xor_sync(0xffffffffu, dd, o);
                }
                if (tx == 0) {
                    g_als[row * 4 + j] = ss;
                    g_ald[row * 4 + j] = dd;
                }
            }
        }
    }
}

// ------------- 40-col output GEMM: same resident-W design, bn+skip fused --------
__global__ void gemm40_kernel(const float* __restrict__ X, const float* __restrict__ W,
                              float* __restrict__ Y,
                              const float* __restrict__ a_s, const float* __restrict__ a_d,
                              const float* __restrict__ skip, int nrows) {
    __shared__ float Ws[40 * WSTRIDE];
    int t  = threadIdx.x;
    int tx = t & 31, ty = t >> 5;
    int row0 = blockIdx.x * 64;

    for (int i = t; i < 40 * 32; i += 256) {
        int c = i >> 5, kg = i & 31;
        *(float4*)&Ws[c * WSTRIDE + 4 * kg] = *(const float4*)&W[c * 128 + 4 * kg];
    }
    __syncthreads();

    float acc[8][2];
#pragma unroll
    for (int i = 0; i < 8; i++) { acc[i][0] = 0.f; acc[i][1] = 0.f; }

    for (int kg = 0; kg < 32; kg++) {
        float4 xv[8];
#pragma unroll
        for (int i = 0; i < 8; i++) {
            int row = row0 + ty + 8 * i;
            float4 v = make_float4(0.f, 0.f, 0.f, 0.f);
            if (row < nrows) {
                float4 xr = *(const float4*)&X[row * 128 + 4 * kg];
                float4 sk = *(const float4*)&skip[row * 128 + 4 * kg];
                int c = 4 * kg;
                float s0 = fmaxf(fmaf(sk.x, g_scale[c],     g_shift[c]),     0.f);
                float s1 = fmaxf(fmaf(sk.y, g_scale[c + 1], g_shift[c + 1]), 0.f);
                float s2 = fmaxf(fmaf(sk.z, g_scale[c + 2], g_shift[c + 2]), 0.f);
                float s3 = fmaxf(fmaf(sk.w, g_scale[c + 3], g_shift[c + 3]), 0.f);
                v.x = fmaxf(fmaf(xr.x, g_scale[HC + c],     g_shift[HC + c])     + SKIPC * s0, 0.f);
                v.y = fmaxf(fmaf(xr.y, g_scale[HC + c + 1], g_shift[HC + c + 1]) + SKIPC * s1, 0.f);
                v.z = fmaxf(fmaf(xr.z, g_scale[HC + c + 2], g_shift[HC + c + 2]) + SKIPC * s2, 0.f);
                v.w = fmaxf(fmaf(xr.w, g_scale[HC + c + 3], g_shift[HC + c + 3]) + SKIPC * s3, 0.f);
            }
            xv[i] = v;
        }
        float4 wv0 = *(const float4*)&Ws[tx * WSTRIDE + 4 * kg];
        float4 wv1 = (tx < 8) ? *(const float4*)&Ws[(32 + tx) * WSTRIDE + 4 * kg]
                              : make_float4(0.f, 0.f, 0.f, 0.f);
#pragma unroll
        for (int i = 0; i < 8; i++) {
            acc[i][0] += xv[i].x * wv0.x + xv[i].y * wv0.y + xv[i].z * wv0.z + xv[i].w * wv0.w;
            acc[i][1] += xv[i].x * wv1.x + xv[i].y * wv1.y + xv[i].z * wv1.z + xv[i].w * wv1.w;
        }
    }

    float as0 = a_s[tx],                 ad0 = a_d[tx];
    float as1 = (tx < 8) ? a_s[32 + tx] : 0.f;
    float ad1 = (tx < 8) ? a_d[32 + tx] : 0.f;
#pragma unroll
    for (int i = 0; i < 8; i++) {
        int row = row0 + ty + 8 * i;
        if (row < nrows) {
            Y[row * 40 + tx] = acc[i][0];
            if (tx < 8) Y[row * 40 + 32 + tx] = acc[i][1];
            float ss = acc[i][0] * as0 + acc[i][1] * as1;
            float dd = acc[i][0] * ad0 + acc[i][1] * ad1;
#pragma unroll
            for (int o = 16; o; o >>= 1) {
                ss += __shfl_xor_sync(0xffffffffu, ss, o);
                dd += __shfl_xor_sync(0xffffffffu, dd, o);
            }
            if (tx == 0) { g_als[row] = ss; g_ald[row] = dd; }
        }
    }
}

// ------------- softmax aggregation, one warp per dst node, all 4 heads ---------
__device__ __forceinline__ float lrelu(float e) { return (e > 0.f) ? e : NEGS * e; }

__global__ void agg4_kernel(const float* __restrict__ h,
                            const float* __restrict__ bias,
                            float* __restrict__ outp, int layer) {
    __shared__ float  s_sum[128], s_sq[128];
    __shared__ int    s_colb[8][32];
    __shared__ float4 s_exb[8][32];
    int t = threadIdx.x;
    int w = t >> 5;
    int node = blockIdx.x * 8 + w;
    int lane = t & 31;
    if (t < 128) { s_sum[t] = 0.f; s_sq[t] = 0.f; }
    __syncthreads();

    int s0 = g_rowptr[node], s1 = g_rowptr[node + 1];
    float4 adv = *(const float4*)&g_ald[node * 4];

    float m0 = -1e30f, m1 = -1e30f, m2 = -1e30f, m3 = -1e30f;
    for (int i = s0 + lane; i < s1; i += 32) {
        float4 al = *(const float4*)&g_als[g_col[i] * 4];
        m0 = fmaxf(m0, lrelu(al.x + adv.x));
        m1 = fmaxf(m1, lrelu(al.y + adv.y));
        m2 = fmaxf(m2, lrelu(al.z + adv.z));
        m3 = fmaxf(m3, lrelu(al.w + adv.w));
    }
#pragma unroll
    for (int o = 16; o; o >>= 1) {
        m0 = fmaxf(m0, __shfl_xor_sync(0xffffffffu, m0, o));
        m1 = fmaxf(m1, __shfl_xor_sync(0xffffffffu, m1, o));
        m2 = fmaxf(m2, __shfl_xor_sync(0xffffffffu, m2, o));
        m3 = fmaxf(m3, __shfl_xor_sync(0xffffffffu, m3, o));
    }

    float d0 = 0.f, d1 = 0.f, d2 = 0.f, d3 = 0.f;
    float a0 = 0.f, a1 = 0.f, a2 = 0.f, a3 = 0.f;
    for (int i0 = s0; i0 < s1; i0 += 32) {
        int i = i0 + lane;
        float e0 = 0.f, e1 = 0.f, e2 = 0.f, e3 = 0.f;
        int s = 0;
        if (i < s1) {
            s = g_col[i];
            float4 al = *(const float4*)&g_als[s * 4];
            e0 = expf(lrelu(al.x + adv.x) - m0);
            e1 = expf(lrelu(al.y + adv.y) - m1);
            e2 = expf(lrelu(al.z + adv.z) - m2);
            e3 = expf(lrelu(al.w + adv.w) - m3);
        }
        d0 += e0; d1 += e1; d2 += e2; d3 += e3;
        s_colb[w][lane] = s;
        s_exb[w][lane]  = make_float4(e0, e1, e2, e3);
        __syncwarp();
        int cnt = min(32, s1 - i0);
#pragma unroll 4
        for (int j = 0; j < cnt; j++) {
            int    sj = s_colb[w][j];
            float4 ex = s_exb[w][j];
            const float* hp = h + sj * 128;
            a0 = fmaf(ex.x, hp[lane],      a0);
            a1 = fmaf(ex.y, hp[32 + lane], a1);
            a2 = fmaf(ex.z, hp[64 + lane], a2);
            a3 = fmaf(ex.w, hp[96 + lane], a3);
        }
        __syncwarp();
    }
#pragma unroll
    for (int o = 16; o; o >>= 1) {
        d0 += __shfl_xor_sync(0xffffffffu, d0, o);
        d1 += __shfl_xor_sync(0xffffffffu, d1, o);
        d2 += __shfl_xor_sync(0xffffffffu, d2, o);
        d3 += __shfl_xor_sync(0xffffffffu, d3, o);
    }
    float v0 = a0 / d0 + bias[lane];
    float v1 = a1 / d1 + bias[32 + lane];
    float v2 = a2 / d2 + bias[64 + lane];
    float v3 = a3 / d3 + bias[96 + lane];
    float* op = outp + node * 128;
    op[lane]      = v0;
    op[32 + lane] = v1;
    op[64 + lane] = v2;
    op[96 + lane] = v3;

    atomicAdd(&s_sum[lane],      v0); atomicAdd(&s_sq[lane],      v0 * v0);
    atomicAdd(&s_sum[32 + lane], v1); atomicAdd(&s_sq[32 + lane], v1 * v1);
    atomicAdd(&s_sum[64 + lane], v2); atomicAdd(&s_sq[64 + lane], v2 * v2);
    atomicAdd(&s_sum[96 + lane], v3); atomicAdd(&s_sq[96 + lane], v3 * v3);
    __syncthreads();
    if (t < 128) {
        int slot = (layer * BNSLOTS + (blockIdx.x & (BNSLOTS - 1))) * HC + t;
        atomicAdd(&g_bnpsum[slot], s_sum[t]);
        atomicAdd(&g_bnpsq[slot],  s_sq[t]);
    }
}

// ---------------- output-layer aggregation (1 head, 40 ch) ----------------
__global__ void agg1_kernel(const float* __restrict__ h,
                            const float* __restrict__ bias,
                            float* __restrict__ outp) {
    __shared__ int   s_colb[8][32];
    __shared__ float s_exb[8][32];
    int t = threadIdx.x;
    int w = t >> 5;
    int node = blockIdx.x * 8 + w;
    int lane = t & 31;
    if (node >= NN) return;
    int s0 = g_rowptr[node], s1 = g_rowptr[node + 1];
    float adv = g_ald[node];

    float m = -1e30f;
    for (int i = s0 + lane; i < s1; i += 32)
        m = fmaxf(m, lrelu(g_als[g_col[i]] + adv));
#pragma unroll
    for (int o = 16; o; o >>= 1) m = fmaxf(m, __shfl_xor_sync(0xffffffffu, m, o));

    float denom = 0.f, acc0 = 0.f, acc1 = 0.f;
    for (int i0 = s0; i0 < s1; i0 += 32) {
        int i = i0 + lane;
        float ex = 0.f;
        int s = 0;
        if (i < s1) {
            s = g_col[i];
            ex = expf(lrelu(g_als[s] + adv) - m);
        }
        denom += ex;
        s_colb[w][lane] = s;
        s_exb[w][lane]  = ex;
        __syncwarp();
        int cnt = min(32, s1 - i0);
#pragma unroll 4
        for (int j = 0; j < cnt; j++) {
            int   sj  = s_colb[w][j];
            float exj = s_exb[w][j];
            const float* hp = h + sj * 40;
            acc0 += exj * hp[lane];
            if (lane < 8) acc1 += exj * hp[32 + lane];
        }
        __syncwarp();
    }
#pragma unroll
    for (int o = 16; o; o >>= 1) denom += __shfl_xor_sync(0xffffffffu, denom, o);
    float inv = 1.f / denom;
    outp[node * 40 + lane] = acc0 * inv + bias[lane];
    if (lane < 8) outp[node * 40 + 32 + lane] = acc1 * inv + bias[32 + lane];
}

// ---------------- batchnorm finalize (reduce 32 slots) ----------------
__global__ void bn_fin_kernel(const float* __restrict__ g,
                              const float* __restrict__ be, int layer) {
    int c = threadIdx.x;
    if (c < 128) {
        float s = 0.f, q = 0.f;
        for (int k = 0; k < BNSLOTS; k++) {
            s += g_bnpsum[(layer * BNSLOTS + k) * HC + c];
            q += g_bnpsq[(layer * BNSLOTS + k) * HC + c];
        }
        float mu  = s * (1.f / NN);
        float var = q * (1.f / NN) - mu * mu;
        float sc  = g[c] * rsqrtf(var + EPSI);
        g_scale[layer * HC + c] = sc;
        g_shift[layer * HC + c] = be[c] - mu * sc;
    }
}

// ---------------- launch ----------------
extern "C" void kernel_launch(void* const* d_in, const int* in_sizes, int n_in,
                              void* d_out, int out_size) {
    const float* x   = (const float*)d_in[0];
    const float* W0  = (const float*)d_in[1];
    const float* as0 = (const float*)d_in[2];
    const float* ad0 = (const float*)d_in[3];
    const float* b0  = (const float*)d_in[4];
    const float* g0  = (const float*)d_in[5];
    const float* be0 = (const float*)d_in[6];
    const float* W1  = (const float*)d_in[7];
    const float* as1 = (const float*)d_in[8];
    const float* ad1 = (const float*)d_in[9];
    const float* b1  = (const float*)d_in[10];
    const float* g1  = (const float*)d_in[11];
    const float* be1 = (const float*)d_in[12];
    const float* W2  = (const float*)d_in[13];
    const float* as2 = (const float*)d_in[14];
    const float* ad2 = (const float*)d_in[15];
    const float* b2  = (const float*)d_in[16];
    const int* ei32  = (const int*)d_in[17];

    float *bufA, *bufB, *bufC;
    cudaGetSymbolAddress((void**)&bufA, g_bufA);
    cudaGetSymbolAddress((void**)&bufB, g_bufB);
    cudaGetSymbolAddress((void**)&bufC, g_bufC);
    float* out = (float*)d_out;

    const int WSMEM = 128 * WSTRIDE * 4;   // 67.6 KB dynamic smem
    cudaFuncSetAttribute(gemm128_kernel<0>, cudaFuncAttributeMaxDynamicSharedMemorySize, WSMEM);
    cudaFuncSetAttribute(gemm128_kernel<1>, cudaFuncAttributeMaxDynamicSharedMemorySize, WSMEM);

    // CSR build, gemm0 kept as 4th launch (ncu-profiled: verify barrier fix)
    detect_kernel<<<1, 256>>>(ei32);
    init_kernel<<<(NN + 255) / 256, 256>>>();
    hist_kernel<<<(EE + 255) / 256, 256>>>(ei32);
    gemm128_kernel<0><<<(NN + 63) / 64, 256, WSMEM>>>(x, W0, bufA, as0, ad0, NN);
    scanA_kernel<<<SCAN_BLOCKS, 256>>>();
    scanB_kernel<<<1, 256>>>();
    scanC_kernel<<<SCAN_BLOCKS, 256>>>();
    selfloop_kernel<<<(NN + 255) / 256, 256>>>();
    scatter_kernel<<<(EE + 255) / 256, 256>>>(ei32);

    // ---- layer 0 aggregation (BN stats fused) ----
    agg4_kernel<<<NN / 8, 256>>>(bufA, b0, bufB, 0);
    bn_fin_kernel<<<1, 128>>>(g0, be0, 0);

    // ---- layer 1 (relu(bn0(x)) fused into GEMM load) ----
    gemm128_kernel<1><<<(NN + 63) / 64, 256, WSMEM>>>(bufB, W1, bufA, as1, ad1, NN);
    agg4_kernel<<<NN / 8, 256>>>(bufA, b1, bufC, 1);
    bn_fin_kernel<<<1, 128>>>(g1, be1, 1);

    // ---- layer 2 (bn1 + skip recomputed from bufB, fused into GEMM load) ----
    gemm40_kernel<<<(NN + 63) / 64, 256>>>(bufC, W2, bufA, as2, ad2, bufB, NN);
    agg1_kernel<<<(NN + 7) / 8, 256>>>(bufA, b2, out);
}

// round 9
// speedup vs baseline: 1.7422x; 1.7422x over previous
#include <cuda_runtime.h>
#include <math.h>

#define NN    50000
#define EE    800000
#define ET    (EE + NN)
#define HC    128
#define H4    4
#define EPSI  1e-5f
#define SKIPC 0.5f
#define NEGS  0.2f
#define SCAN_BLOCKS ((NN + 255) / 256)   // 196
#define BNSLOTS 32

// ---------------- static device scratch (no allocations allowed) ----------------
__device__ int   g_is64;
__device__ int   g_count[NN];
__device__ int   g_rowptr[NN + 1];
__device__ int   g_cursor[NN];
__device__ int   g_col[ET];
__device__ int   g_part[SCAN_BLOCKS];
__device__ int   g_partoff[SCAN_BLOCKS];
__device__ __align__(16) float g_bufA[NN * HC];
__device__ __align__(16) float g_bufB[NN * HC];
__device__ __align__(16) float g_bufC[NN * HC];
__device__ __align__(16) float g_als[NN * H4];
__device__ __align__(16) float g_ald[NN * H4];
__device__ float g_bnpsum[2 * BNSLOTS * HC];
__device__ float g_bnpsq[2 * BNSLOTS * HC];
__device__ float g_scale[2 * HC];
__device__ float g_shift[2 * HC];

// edge_index may be int32 or int64 (jax x64 flag dependent). Detect on device.
__global__ void detect_kernel(const int* __restrict__ ei32) {
    __shared__ int any;
    int t = threadIdx.x;
    if (t == 0) any = 0;
    __syncthreads();
    if (ei32[2 * t + 1] != 0) atomicOr(&any, 1);
    __syncthreads();
    if (t == 0) g_is64 = any ? 0 : 1;
}

__device__ __forceinline__ int ld_edge(const int* __restrict__ ei32, int pos) {
    return g_is64 ? ei32[2 * pos] : ei32[pos];
}

// ---------------- CSR construction ----------------
__global__ void init_kernel() {
    int i = blockIdx.x * blockDim.x + threadIdx.x;
    if (i < NN) g_count[i] = 1;               // self-loop pre-counted
    if (i < 2 * BNSLOTS * HC) { g_bnpsum[i] = 0.f; g_bnpsq[i] = 0.f; }
}

__global__ void hist_kernel(const int* __restrict__ ei32) {
    int e = blockIdx.x * blockDim.x + threadIdx.x;
    if (e < EE) {
        int d = ld_edge(ei32, EE + e);
        if ((unsigned)d < NN) atomicAdd(&g_count[d], 1);
    }
}

__global__ void scanA_kernel() {            // per-block sums
    __shared__ int sm[256];
    int t = threadIdx.x;
    int idx = blockIdx.x * 256 + t;
    sm[t] = (idx < NN) ? g_count[idx] : 0;
    __syncthreads();
    for (int o = 128; o; o >>= 1) {
        if (t < o) sm[t] += sm[t + o];
        __syncthreads();
    }
    if (t == 0) g_part[blockIdx.x] = sm[0];
}

__global__ void scanB_kernel() {            // exclusive scan of block sums
    __shared__ int sm[256];
    int t = threadIdx.x;
    sm[t] = (t < SCAN_BLOCKS) ? g_part[t] : 0;
    __syncthreads();
    for (int o = 1; o < 256; o <<= 1) {
        int v = (t >= o) ? sm[t - o] : 0;
        __syncthreads();
        sm[t] += v;
        __syncthreads();
    }
    if (t < SCAN_BLOCKS) g_partoff[t] = (t > 0) ? sm[t - 1] : 0;
}

__global__ void scanC_kernel() {            // in-block inclusive scan + offset
    __shared__ int sm[256];
    int t = threadIdx.x;
    int idx = blockIdx.x * 256 + t;
    int v = (idx < NN) ? g_count[idx] : 0;
    sm[t] = v;
    __syncthreads();
    for (int o = 1; o < 256; o <<= 1) {
        int u = (t >= o) ? sm[t - o] : 0;
        __syncthreads();
        sm[t] += u;
        __syncthreads();
    }
    if (idx < NN) g_rowptr[idx + 1] = g_partoff[blockIdx.x] + sm[t];
    if (idx == 0) g_rowptr[0] = 0;
}

__global__ void selfloop_kernel() {
    int n = blockIdx.x * blockDim.x + threadIdx.x;
    if (n < NN) {
        int p = g_rowptr[n];
        g_col[p] = n;                          // self-loop first
        g_cursor[n] = p + 1;
    }
}

__global__ void scatter_kernel(const int* __restrict__ ei32) {
    int e = blockIdx.x * blockDim.x + threadIdx.x;
    if (e < EE) {
        int s = ld_edge(ei32, e);
        int d = ld_edge(ei32, EE + e);
        if ((unsigned)d < NN && (unsigned)s < NN) {
            int pos = atomicAdd(&g_cursor[d], 1);
            g_col[pos] = s;
        }
    }
}

// ------------- 128-col GEMM, software-pipelined (reg prefetch of next chunk) ----
// 64x128 block tile, thread (tx,ty): rows ty+8i, cols 4tx..4tx+3.
// SMEM W transposed [kk][c]. XFORM: 0 = none, 1 = v -> relu(bn0(v))
template <int XFORM>
__global__ __launch_bounds__(256, 2)
void gemm128_kernel(const float* __restrict__ X, const float* __restrict__ W,
                    float* __restrict__ Y,
                    const float* __restrict__ a_s, const float* __restrict__ a_d,
                    int nrows) {
    __shared__ float Ws[32][132];
    __shared__ float Xs[64][36];
    int t  = threadIdx.x;
    int tx = t & 31, ty = t >> 5;
    int row0 = blockIdx.x * 64;

    float acc[8][4];
#pragma unroll
    for (int i = 0; i < 8; i++)
#pragma unroll
        for (int j = 0; j < 4; j++) acc[i][j] = 0.f;

    float4 wpre[4], xpre[2];
    // prefetch chunk 0
#pragma unroll
    for (int q = 0; q < 4; q++) {
        int idx = t + 256 * q, c = idx >> 3, f4 = idx & 7;
        wpre[q] = *(const float4*)&W[c * 128 + 4 * f4];
    }
#pragma unroll
    for (int q = 0; q < 2; q++) {
        int idx = t + 256 * q, r = idx >> 3, f4 = idx & 7;
        int row = row0 + r;
        xpre[q] = (row < nrows) ? *(const float4*)&X[row * 128 + 4 * f4]
                                : make_float4(0.f, 0.f, 0.f, 0.f);
    }

    for (int kc = 0; kc < 128; kc += 32) {
        // store prefetched chunk to smem
#pragma unroll
        for (int q = 0; q < 4; q++) {
            int idx = t + 256 * q, c = idx >> 3, f4 = idx & 7;
            Ws[4 * f4 + 0][c] = wpre[q].x;
            Ws[4 * f4 + 1][c] = wpre[q].y;
            Ws[4 * f4 + 2][c] = wpre[q].z;
            Ws[4 * f4 + 3][c] = wpre[q].w;
        }
#pragma unroll
        for (int q = 0; q < 2; q++) {
            int idx = t + 256 * q, r = idx >> 3, f4 = idx & 7;
            float4 v = xpre[q];
            if (XFORM == 1) {
                int c = kc + 4 * f4;
                v.x = fmaxf(fmaf(v.x, g_scale[c],     g_shift[c]),     0.f);
                v.y = fmaxf(fmaf(v.y, g_scale[c + 1], g_shift[c + 1]), 0.f);
                v.z = fmaxf(fmaf(v.z, g_scale[c + 2], g_shift[c + 2]), 0.f);
                v.w = fmaxf(fmaf(v.w, g_scale[c + 3], g_shift[c + 3]), 0.f);
            }
            *(float4*)&Xs[r][4 * f4] = v;
        }
        __syncthreads();
        // prefetch next chunk (LDGs overlap compute below)
        if (kc < 96) {
            int kn = kc + 32;
#pragma unroll
            for (int q = 0; q < 4; q++) {
                int idx = t + 256 * q, c = idx >> 3, f4 = idx & 7;
                wpre[q] = *(const float4*)&W[c * 128 + kn + 4 * f4];
            }
#pragma unroll
            for (int q = 0; q < 2; q++) {
                int idx = t + 256 * q, r = idx >> 3, f4 = idx & 7;
                int row = row0 + r;
                xpre[q] = (row < nrows) ? *(const float4*)&X[row * 128 + kn + 4 * f4]
                                        : make_float4(0.f, 0.f, 0.f, 0.f);
            }
        }
        // compute current chunk
#pragma unroll
        for (int kk = 0; kk < 32; kk += 4) {
            float4 wq[4];
#pragma unroll
            for (int q = 0; q < 4; q++)
                wq[q] = *(const float4*)&Ws[kk + q][4 * tx];
#pragma unroll
            for (int i = 0; i < 8; i++) {
                float4 xv = *(const float4*)&Xs[ty + 8 * i][kk];
                acc[i][0] += xv.x * wq[0].x + xv.y * wq[1].x + xv.z * wq[2].x + xv.w * wq[3].x;
                acc[i][1] += xv.x * wq[0].y + xv.y * wq[1].y + xv.z * wq[2].y + xv.w * wq[3].y;
                acc[i][2] += xv.x * wq[0].z + xv.y * wq[1].z + xv.z * wq[2].z + xv.w * wq[3].z;
                acc[i][3] += xv.x * wq[0].w + xv.y * wq[1].w + xv.z * wq[2].w + xv.w * wq[3].w;
            }
        }
        __syncthreads();
    }
    // store (float4) + fused attention-logit epilogue (reduce within lane-groups of 8)
    float4 as4 = *(const float4*)&a_s[4 * tx];
    float4 ad4 = *(const float4*)&a_d[4 * tx];
    int hd = tx >> 3;
#pragma unroll
    for (int i = 0; i < 8; i++) {
        int row = row0 + ty + 8 * i;
        if (row < nrows) {
            *(float4*)&Y[row * 128 + 4 * tx] =
                make_float4(acc[i][0], acc[i][1], acc[i][2], acc[i][3]);
            float ps = acc[i][0] * as4.x + acc[i][1] * as4.y +
                       acc[i][2] * as4.z + acc[i][3] * as4.w;
            float pd = acc[i][0] * ad4.x + acc[i][1] * ad4.y +
                       acc[i][2] * ad4.z + acc[i][3] * ad4.w;
#pragma unroll
            for (int o = 1; o < 8; o <<= 1) {
                ps += __shfl_xor_sync(0xffffffffu, ps, o);
                pd += __shfl_xor_sync(0xffffffffu, pd, o);
            }
            if ((tx & 7) == 0) {
                g_als[row * 4 + hd] = ps;
                g_ald[row * 4 + hd] = pd;
            }
        }
    }
}

// ------------- 40-col output GEMM (32-row blocks) with bn1+skip fused input -----
__global__ void gemm40_kernel(const float* __restrict__ X, const float* __restrict__ W,
                              float* __restrict__ Y,
                              const float* __restrict__ a_s, const float* __restrict__ a_d,
                              const float* __restrict__ skip, int nrows) {
    __shared__ float Ws[40][68];
    __shared__ float Xs[32][68];
    int t  = threadIdx.x;            // 256 threads
    int tx = t & 31, ty = t >> 5;
    int row0 = blockIdx.x * 32;

    float acc[4][2];
#pragma unroll
    for (int i = 0; i < 4; i++) { acc[i][0] = 0.f; acc[i][1] = 0.f; }

    for (int kc = 0; kc < 128; kc += 64) {
        for (int i = t; i < 40 * 64; i += 256) {
            int c = i >> 6, kk = i & 63;
            Ws[c][kk] = W[c * 128 + kc + kk];
        }
        for (int i = t; i < 32 * 64; i += 256) {
            int r = i >> 6, kk = i & 63;
            int row = row0 + r;
            float v = 0.f;
            if (row < nrows) {
                int gi = row * 128 + kc + kk;
                int c  = kc + kk;
                float sk = fmaxf(fmaf(skip[gi], g_scale[c], g_shift[c]), 0.f);
                v = fmaxf(fmaf(X[gi], g_scale[HC + c], g_shift[HC + c]) + SKIPC * sk, 0.f);
            }
            Xs[r][kk] = v;
        }
        __syncthreads();
#pragma unroll
        for (int kk = 0; kk < 64; kk += 4) {
            float4 xv[4];
#pragma unroll
            for (int i = 0; i < 4; i++)
                xv[i] = *(const float4*)&Xs[ty + 8 * i][kk];
#pragma unroll
            for (int j = 0; j < 2; j++) {
                int c = tx + 32 * j;
                if (c < 40) {
                    float4 wv = *(const float4*)&Ws[c][kk];
#pragma unroll
                    for (int i = 0; i < 4; i++) {
                        acc[i][j] += xv[i].x * wv.x + xv[i].y * wv.y +
                                     xv[i].z * wv.z + xv[i].w * wv.w;
                    }
                }
            }
        }
        __syncthreads();
    }
    float as0 = a_s[tx],                 ad0 = a_d[tx];
    float as1 = (tx < 8) ? a_s[32 + tx] : 0.f;
    float ad1 = (tx < 8) ? a_d[32 + tx] : 0.f;
#pragma unroll
    for (int i = 0; i < 4; i++) {
        int row = row0 + ty + 8 * i;
        if (row < nrows) {
            Y[row * 40 + tx] = acc[i][0];
            if (tx < 8) Y[row * 40 + 32 + tx] = acc[i][1];
            float ss = acc[i][0] * as0 + acc[i][1] * as1;
            float dd = acc[i][0] * ad0 + acc[i][1] * ad1;
#pragma unroll
            for (int o = 16; o; o >>= 1) {
                ss += __shfl_xor_sync(0xffffffffu, ss, o);
                dd += __shfl_xor_sync(0xffffffffu, dd, o);
            }
            if (tx == 0) { g_als[row] = ss; g_ald[row] = dd; }
        }
    }
}

// ------------- softmax aggregation, one warp per dst node, all 4 heads ---------
// Single pass: logits are O(10), so exp without max-subtraction is fp32-safe
// and mathematically identical to the max-shifted softmax.
__device__ __forceinline__ float lrelu(float e) { return (e > 0.f) ? e : NEGS * e; }

__global__ void agg4_kernel(const float* __restrict__ h,
                            const float* __restrict__ bias,
                            float* __restrict__ outp, int layer) {
    __shared__ float  s_sum[128], s_sq[128];
    __shared__ int    s_colb[8][32];
    __shared__ float4 s_exb[8][32];
    int t = threadIdx.x;
    int w = t >> 5;
    int node = blockIdx.x * 8 + w;
    int lane = t & 31;
    if (t < 128) { s_sum[t] = 0.f; s_sq[t] = 0.f; }
    __syncthreads();

    int s0 = g_rowptr[node], s1 = g_rowptr[node + 1];
    float4 adv = *(const float4*)&g_ald[node * 4];

    float d0 = 0.f, d1 = 0.f, d2 = 0.f, d3 = 0.f;
    float a0 = 0.f, a1 = 0.f, a2 = 0.f, a3 = 0.f;
    for (int i0 = s0; i0 < s1; i0 += 32) {
        int i = i0 + lane;
        float e0 = 0.f, e1 = 0.f, e2 = 0.f, e3 = 0.f;
        int s = 0;
        if (i < s1) {
            s = g_col[i];
            float4 al = *(const float4*)&g_als[s * 4];
            e0 = expf(lrelu(al.x + adv.x));
            e1 = expf(lrelu(al.y + adv.y));
            e2 = expf(lrelu(al.z + adv.z));
            e3 = expf(lrelu(al.w + adv.w));
        }
        d0 += e0; d1 += e1; d2 += e2; d3 += e3;
        s_colb[w][lane] = s;
        s_exb[w][lane]  = make_float4(e0, e1, e2, e3);
        __syncwarp();
        int cnt = min(32, s1 - i0);
#pragma unroll 4
        for (int j = 0; j < cnt; j++) {
            int    sj = s_colb[w][j];
            float4 ex = s_exb[w][j];
            const float* hp = h + sj * 128;
            a0 = fmaf(ex.x, hp[lane],      a0);
            a1 = fmaf(ex.y, hp[32 + lane], a1);
            a2 = fmaf(ex.z, hp[64 + lane], a2);
            a3 = fmaf(ex.w, hp[96 + lane], a3);
        }
        __syncwarp();
    }
#pragma unroll
    for (int o = 16; o; o >>= 1) {
        d0 += __shfl_xor_sync(0xffffffffu, d0, o);
        d1 += __shfl_xor_sync(0xffffffffu, d1, o);
        d2 += __shfl_xor_sync(0xffffffffu, d2, o);
        d3 += __shfl_xor_sync(0xffffffffu, d3, o);
    }
    float v0 = a0 / d0 + bias[lane];
    float v1 = a1 / d1 + bias[32 + lane];
    float v2 = a2 / d2 + bias[64 + lane];
    float v3 = a3 / d3 + bias[96 + lane];
    float* op = outp + node * 128;
    op[lane]      = v0;
    op[32 + lane] = v1;
    op[64 + lane] = v2;
    op[96 + lane] = v3;

    atomicAdd(&s_sum[lane],      v0); atomicAdd(&s_sq[lane],      v0 * v0);
    atomicAdd(&s_sum[32 + lane], v1); atomicAdd(&s_sq[32 + lane], v1 * v1);
    atomicAdd(&s_sum[64 + lane], v2); atomicAdd(&s_sq[64 + lane], v2 * v2);
    atomicAdd(&s_sum[96 + lane], v3); atomicAdd(&s_sq[96 + lane], v3 * v3);
    __syncthreads();
    if (t < 128) {
        int slot = (layer * BNSLOTS + (blockIdx.x & (BNSLOTS - 1))) * HC + t;
        atomicAdd(&g_bnpsum[slot], s_sum[t]);
        atomicAdd(&g_bnpsq[slot],  s_sq[t]);
    }
}

// ---------------- output-layer aggregation (1 head, 40 ch), single pass --------
__global__ void agg1_kernel(const float* __restrict__ h,
                            const float* __restrict__ bias,
                            float* __restrict__ outp) {
    __shared__ int   s_colb[8][32];
    __shared__ float s_exb[8][32];
    int t = threadIdx.x;
    int w = t >> 5;
    int node = blockIdx.x * 8 + w;
    int lane = t & 31;
    if (node >= NN) return;
    int s0 = g_rowptr[node], s1 = g_rowptr[node + 1];
    float adv = g_ald[node];

    float denom = 0.f, acc0 = 0.f, acc1 = 0.f;
    for (int i0 = s0; i0 < s1; i0 += 32) {
        int i = i0 + lane;
        float ex = 0.f;
        int s = 0;
        if (i < s1) {
            s = g_col[i];
            ex = expf(lrelu(g_als[s] + adv));
        }
        denom += ex;
        s_colb[w][lane] = s;
        s_exb[w][lane]  = ex;
        __syncwarp();
        int cnt = min(32, s1 - i0);
#pragma unroll 4
        for (int j = 0; j < cnt; j++) {
            int   sj  = s_colb[w][j];
            float exj = s_exb[w][j];
            const float* hp = h + sj * 40;
            acc0 += exj * hp[lane];
            if (lane < 8) acc1 += exj * hp[32 + lane];
        }
        __syncwarp();
    }
#pragma unroll
    for (int o = 16; o; o >>= 1) denom += __shfl_xor_sync(0xffffffffu, denom, o);
    float inv = 1.f / denom;
    outp[node * 40 + lane] = acc0 * inv + bias[lane];
    if (lane < 8) outp[node * 40 + 32 + lane] = acc1 * inv + bias[32 + lane];
}

// ---------------- batchnorm finalize (reduce 32 slots) ----------------
__global__ void bn_fin_kernel(const float* __restrict__ g,
                              const float* __restrict__ be, int layer) {
    int c = threadIdx.x;
    if (c < 128) {
        float s = 0.f, q = 0.f;
        for (int k = 0; k < BNSLOTS; k++) {
            s += g_bnpsum[(layer * BNSLOTS + k) * HC + c];
            q += g_bnpsq[(layer * BNSLOTS + k) * HC + c];
        }
        float mu  = s * (1.f / NN);
        float var = q * (1.f / NN) - mu * mu;
        float sc  = g[c] * rsqrtf(var + EPSI);
        g_scale[layer * HC + c] = sc;
        g_shift[layer * HC + c] = be[c] - mu * sc;
    }
}

// ---------------- launch ----------------
extern "C" void kernel_launch(void* const* d_in, const int* in_sizes, int n_in,
                              void* d_out, int out_size) {
    const float* x   = (const float*)d_in[0];
    const float* W0  = (const float*)d_in[1];
    const float* as0 = (const float*)d_in[2];
    const float* ad0 = (const float*)d_in[3];
    const float* b0  = (const float*)d_in[4];
    const float* g0  = (const float*)d_in[5];
    const float* be0 = (const float*)d_in[6];
    const float* W1  = (const float*)d_in[7];
    const float* as1 = (const float*)d_in[8];
    const float* ad1 = (const float*)d_in[9];
    const float* b1  = (const float*)d_in[10];
    const float* g1  = (const float*)d_in[11];
    const float* be1 = (const float*)d_in[12];
    const float* W2  = (const float*)d_in[13];
    const float* as2 = (const float*)d_in[14];
    const float* ad2 = (const float*)d_in[15];
    const float* b2  = (const float*)d_in[16];
    const int* ei32  = (const int*)d_in[17];

    float *bufA, *bufB, *bufC;
    cudaGetSymbolAddress((void**)&bufA, g_bufA);
    cudaGetSymbolAddress((void**)&bufB, g_bufB);
    cudaGetSymbolAddress((void**)&bufC, g_bufC);
    float* out = (float*)d_out;

    // CSR build, gemm0 kept as 4th launch (ncu-profiled: verify pipeline)
    detect_kernel<<<1, 256>>>(ei32);
    init_kernel<<<(NN + 255) / 256, 256>>>();
    hist_kernel<<<(EE + 255) / 256, 256>>>(ei32);
    gemm128_kernel<0><<<(NN + 63) / 64, 256>>>(x, W0, bufA, as0, ad0, NN);
    scanA_kernel<<<SCAN_BLOCKS, 256>>>();
    scanB_kernel<<<1, 256>>>();
    scanC_kernel<<<SCAN_BLOCKS, 256>>>();
    selfloop_kernel<<<(NN + 255) / 256, 256>>>();
    scatter_kernel<<<(EE + 255) / 256, 256>>>(ei32);

    // ---- layer 0 aggregation (BN stats fused) ----
    agg4_kernel<<<NN / 8, 256>>>(bufA, b0, bufB, 0);
    bn_fin_kernel<<<1, 128>>>(g0, be0, 0);

    // ---- layer 1 (relu(bn0(x)) fused into GEMM load) ----
    gemm128_kernel<1><<<(NN + 63) / 64, 256>>>(bufB, W1, bufA, as1, ad1, NN);
    agg4_kernel<<<NN / 8, 256>>>(bufA, b1, bufC, 1);
    bn_fin_kernel<<<1, 128>>>(g1, be1, 1);

    // ---- layer 2 (bn1 + skip recomputed from bufB, fused into GEMM load) ----
    gemm40_kernel<<<(NN + 31) / 32, 256>>>(bufC, W2, bufA, as2, ad2, bufB, NN);
    agg1_kernel<<<(NN + 7) / 8, 256>>>(bufA, b2, out);
}

// round 11
// speedup vs baseline: 1.8245x; 1.0472x over previous
#include <cuda_runtime.h>
#include <math.h>

#define NN    50000
#define EE    800000
#define ET    (EE + NN)
#define HC    128
#define H4    4
#define EPSI  1e-5f
#define SKIPC 0.5f
#define NEGS  0.2f
#define SCAN_BLOCKS ((NN + 255) / 256)   // 196
#define BNSLOTS 32

// ---------------- static device scratch (no allocations allowed) ----------------
__device__ int   g_is64;
__device__ int   g_count[NN];
__device__ int   g_rowptr[NN + 1];
__device__ int   g_cursor[NN];
__device__ int   g_col[ET];
__device__ int   g_part[SCAN_BLOCKS];
__device__ int   g_partoff[SCAN_BLOCKS];
__device__ __align__(16) float g_bufA[NN * HC];
__device__ __align__(16) float g_bufB[NN * HC];
__device__ __align__(16) float g_bufC[NN * HC];
__device__ __align__(16) float g_als[NN * H4];
__device__ __align__(16) float g_ald[NN * H4];
__device__ float g_bnpsum[2 * BNSLOTS * HC];
__device__ float g_bnpsq[2 * BNSLOTS * HC];
__device__ float g_scale[2 * HC];
__device__ float g_shift[2 * HC];

// packed fp32x2 helpers (SASS FFMA2 path, PTX-only per sm_103a quickref)
__device__ __forceinline__ unsigned long long f32x2_dup(float a) {
    unsigned long long d;
    asm("mov.b64 %0, {%1, %1};" : "=l"(d) : "f"(a));
    return d;
}
__device__ __forceinline__ void f32x2_fma(unsigned long long& d,
                                          unsigned long long a,
                                          unsigned long long b) {
    asm("fma.rn.f32x2 %0, %1, %2, %0;" : "+l"(d) : "l"(a), "l"(b));
}
__device__ __forceinline__ void f32x2_unpack(unsigned long long v, float& lo, float& hi) {
    asm("mov.b64 {%0, %1}, %2;" : "=f"(lo), "=f"(hi) : "l"(v));
}

// edge_index may be int32 or int64 (jax x64 flag dependent). Detect on device.
__global__ void detect_kernel(const int* __restrict__ ei32) {
    __shared__ int any;
    int t = threadIdx.x;
    if (t == 0) any = 0;
    __syncthreads();
    if (ei32[2 * t + 1] != 0) atomicOr(&any, 1);
    __syncthreads();
    if (t == 0) g_is64 = any ? 0 : 1;
}

__device__ __forceinline__ int ld_edge(const int* __restrict__ ei32, int pos) {
    return g_is64 ? ei32[2 * pos] : ei32[pos];
}

// ---------------- CSR construction ----------------
__global__ void init_kernel() {
    int i = blockIdx.x * blockDim.x + threadIdx.x;
    if (i < NN) g_count[i] = 1;               // self-loop pre-counted
    if (i < 2 * BNSLOTS * HC) { g_bnpsum[i] = 0.f; g_bnpsq[i] = 0.f; }
}

__global__ void hist_kernel(const int* __restrict__ ei32) {
    int e = blockIdx.x * blockDim.x + threadIdx.x;
    if (e < EE) {
        int d = ld_edge(ei32, EE + e);
        if ((unsigned)d < NN) atomicAdd(&g_count[d], 1);
    }
}

__global__ void scanA_kernel() {            // per-block sums
    __shared__ int sm[256];
    int t = threadIdx.x;
    int idx = blockIdx.x * 256 + t;
    sm[t] = (idx < NN) ? g_count[idx] : 0;
    __syncthreads();
    for (int o = 128; o; o >>= 1) {
        if (t < o) sm[t] += sm[t + o];
        __syncthreads();
    }
    if (t == 0) g_part[blockIdx.x] = sm[0];
}

__global__ void scanB_kernel() {            // exclusive scan of block sums
    __shared__ int sm[256];
    int t = threadIdx.x;
    sm[t] = (t < SCAN_BLOCKS) ? g_part[t] : 0;
    __syncthreads();
    for (int o = 1; o < 256; o <<= 1) {
        int v = (t >= o) ? sm[t - o] : 0;
        __syncthreads();
        sm[t] += v;
        __syncthreads();
    }
    if (t < SCAN_BLOCKS) g_partoff[t] = (t > 0) ? sm[t - 1] : 0;
}

__global__ void scanC_kernel() {            // in-block inclusive scan + offset
    __shared__ int sm[256];
    int t = threadIdx.x;
    int idx = blockIdx.x * 256 + t;
    int v = (idx < NN) ? g_count[idx] : 0;
    sm[t] = v;
    __syncthreads();
    for (int o = 1; o < 256; o <<= 1) {
        int u = (t >= o) ? sm[t - o] : 0;
        __syncthreads();
        sm[t] += u;
        __syncthreads();
    }
    if (idx < NN) g_rowptr[idx + 1] = g_partoff[blockIdx.x] + sm[t];
    if (idx == 0) g_rowptr[0] = 0;
}

__global__ void selfloop_kernel() {
    int n = blockIdx.x * blockDim.x + threadIdx.x;
    if (n < NN) {
        int p = g_rowptr[n];
        g_col[p] = n;                          // self-loop first
        g_cursor[n] = p + 1;
    }
}

__global__ void scatter_kernel(const int* __restrict__ ei32) {
    int e = blockIdx.x * blockDim.x + threadIdx.x;
    if (e < EE) {
        int s = ld_edge(ei32, e);
        int d = ld_edge(ei32, EE + e);
        if ((unsigned)d < NN && (unsigned)s < NN) {
            int pos = atomicAdd(&g_cursor[d], 1);
            g_col[pos] = s;
        }
    }
}

// ------------- 128-col GEMM, pipelined, row-pair packed FFMA2 -------------------
// 64x128 block tile. Thread (tx,ty): cols 4tx..4tx+3, row quads {4ty..4ty+3,
// 4ty+32..4ty+35} held as f32x2 row-pairs. Xs transposed [kk][row], row stride
// 68 floats = 272B (16B-aligned) so ulonglong2 loads are legal.
// XFORM: 0 = none, 1 = v -> relu(bn0(v))
template <int XFORM>
__global__ __launch_bounds__(256, 2)
void gemm128_kernel(const float* __restrict__ X, const float* __restrict__ W,
                    float* __restrict__ Y,
                    const float* __restrict__ a_s, const float* __restrict__ a_d,
                    int nrows) {
    __shared__ __align__(16) float Ws[32][132];   // [kk][c]
    __shared__ __align__(16) float Xs[32][68];    // [kk][row] (transposed, 16B rows)
    int t  = threadIdx.x;
    int tx = t & 31, ty = t >> 5;
    int row0 = blockIdx.x * 64;

    unsigned long long acc2[2][2][4];   // [quad][pair][col] f32x2 (lo=even row)
    unsigned long long zz = f32x2_dup(0.f);
#pragma unroll
    for (int q = 0; q < 2; q++)
#pragma unroll
        for (int h = 0; h < 2; h++)
#pragma unroll
            for (int j = 0; j < 4; j++) acc2[q][h][j] = zz;

    float4 wpre[4], xpre[2];
    // prefetch chunk 0
#pragma unroll
    for (int q = 0; q < 4; q++) {
        int idx = t + 256 * q, c = idx >> 3, f4 = idx & 7;
        wpre[q] = *(const float4*)&W[c * 128 + 4 * f4];
    }
#pragma unroll
    for (int q = 0; q < 2; q++) {
        int idx = t + 256 * q, r = idx >> 3, f4 = idx & 7;
        int row = row0 + r;
        xpre[q] = (row < nrows) ? *(const float4*)&X[row * 128 + 4 * f4]
                                : make_float4(0.f, 0.f, 0.f, 0.f);
    }

    for (int kc = 0; kc < 128; kc += 32) {
        // store prefetched chunk to smem
#pragma unroll
        for (int q = 0; q < 4; q++) {
            int idx = t + 256 * q, c = idx >> 3, f4 = idx & 7;
            Ws[4 * f4 + 0][c] = wpre[q].x;
            Ws[4 * f4 + 1][c] = wpre[q].y;
            Ws[4 * f4 + 2][c] = wpre[q].z;
            Ws[4 * f4 + 3][c] = wpre[q].w;
        }
#pragma unroll
        for (int q = 0; q < 2; q++) {
            int idx = t + 256 * q, r = idx >> 3, f4 = idx & 7;
            float4 v = xpre[q];
            if (XFORM == 1) {
                int c = kc + 4 * f4;
                v.x = fmaxf(fmaf(v.x, g_scale[c],     g_shift[c]),     0.f);
                v.y = fmaxf(fmaf(v.y, g_scale[c + 1], g_shift[c + 1]), 0.f);
                v.z = fmaxf(fmaf(v.z, g_scale[c + 2], g_shift[c + 2]), 0.f);
                v.w = fmaxf(fmaf(v.w, g_scale[c + 3], g_shift[c + 3]), 0.f);
            }
            Xs[4 * f4 + 0][r] = v.x;    // transposed scatter
            Xs[4 * f4 + 1][r] = v.y;
            Xs[4 * f4 + 2][r] = v.z;
            Xs[4 * f4 + 3][r] = v.w;
        }
        __syncthreads();
        // prefetch next chunk (LDGs overlap compute below)
        if (kc < 96) {
            int kn = kc + 32;
#pragma unroll
            for (int q = 0; q < 4; q++) {
                int idx = t + 256 * q, c = idx >> 3, f4 = idx & 7;
                wpre[q] = *(const float4*)&W[c * 128 + kn + 4 * f4];
            }
#pragma unroll
            for (int q = 0; q < 2; q++) {
                int idx = t + 256 * q, r = idx >> 3, f4 = idx & 7;
                int row = row0 + r;
                xpre[q] = (row < nrows) ? *(const float4*)&X[row * 128 + kn + 4 * f4]
                                        : make_float4(0.f, 0.f, 0.f, 0.f);
            }
        }
        // compute current chunk: per k, 2 broadcast 16B LDS (4 row-pairs),
        // 1 LDS.128 (4 cols), 4 dup-movs, 16 FFMA2.
#pragma unroll 8
        for (int kk = 0; kk < 32; kk++) {
            ulonglong2 xq0 = *(const ulonglong2*)&Xs[kk][4 * ty];        // rows 4ty..4ty+3
            ulonglong2 xq1 = *(const ulonglong2*)&Xs[kk][4 * ty + 32];   // rows 4ty+32..+35
            float4 wv = *(const float4*)&Ws[kk][4 * tx];
            unsigned long long wd[4];
            wd[0] = f32x2_dup(wv.x);
            wd[1] = f32x2_dup(wv.y);
            wd[2] = f32x2_dup(wv.z);
            wd[3] = f32x2_dup(wv.w);
#pragma unroll
            for (int j = 0; j < 4; j++) {
                f32x2_fma(acc2[0][0][j], xq0.x, wd[j]);
                f32x2_fma(acc2[0][1][j], xq0.y, wd[j]);
                f32x2_fma(acc2[1][0][j], xq1.x, wd[j]);
                f32x2_fma(acc2[1][1][j], xq1.y, wd[j]);
            }
        }
        __syncthreads();
    }

    // epilogue: unpack, store float4, fused logits (8-lane-group reduction)
    float4 as4 = *(const float4*)&a_s[4 * tx];
    float4 ad4 = *(const float4*)&a_d[4 * tx];
    int hd = tx >> 3;
#pragma unroll
    for (int q = 0; q < 2; q++) {
        int rbase = row0 + 4 * ty + 32 * q;
#pragma unroll
        for (int h = 0; h < 2; h++) {
            float lo[4], hi[4];
#pragma unroll
            for (int j = 0; j < 4; j++) f32x2_unpack(acc2[q][h][j], lo[j], hi[j]);
#pragma unroll
            for (int e = 0; e < 2; e++) {
                int row = rbase + 2 * h + e;
                float* v = e ? hi : lo;
                if (row < nrows) {
                    *(float4*)&Y[row * 128 + 4 * tx] =
                        make_float4(v[0], v[1], v[2], v[3]);
                    float ps = v[0] * as4.x + v[1] * as4.y + v[2] * as4.z + v[3] * as4.w;
                    float pd = v[0] * ad4.x + v[1] * ad4.y + v[2] * ad4.z + v[3] * ad4.w;
#pragma unroll
                    for (int o = 1; o < 8; o <<= 1) {
                        ps += __shfl_xor_sync(0xffffffffu, ps, o);
                        pd += __shfl_xor_sync(0xffffffffu, pd, o);
                    }
                    if ((tx & 7) == 0) {
                        g_als[row * 4 + hd] = ps;
                        g_ald[row * 4 + hd] = pd;
                    }
                }
            }
        }
    }
}

// ------------- 40-col output GEMM (32-row blocks) with bn1+skip fused input -----
__global__ void gemm40_kernel(const float* __restrict__ X, const float* __restrict__ W,
                              float* __restrict__ Y,
                              const float* __restrict__ a_s, const float* __restrict__ a_d,
                              const float* __restrict__ skip, int nrows) {
    __shared__ float Ws[40][68];
    __shared__ float Xs[32][68];
    int t  = threadIdx.x;            // 256 threads
    int tx = t & 31, ty = t >> 5;
    int row0 = blockIdx.x * 32;

    float acc[4][2];
#pragma unroll
    for (int i = 0; i < 4; i++) { acc[i][0] = 0.f; acc[i][1] = 0.f; }

    for (int kc = 0; kc < 128; kc += 64) {
        for (int i = t; i < 40 * 64; i += 256) {
            int c = i >> 6, kk = i & 63;
            Ws[c][kk] = W[c * 128 + kc + kk];
        }
        for (int i = t; i < 32 * 64; i += 256) {
            int r = i >> 6, kk = i & 63;
            int row = row0 + r;
            float v = 0.f;
            if (row < nrows) {
                int gi = row * 128 + kc + kk;
                int c  = kc + kk;
                float sk = fmaxf(fmaf(skip[gi], g_scale[c], g_shift[c]), 0.f);
                v = fmaxf(fmaf(X[gi], g_scale[HC + c], g_shift[HC + c]) + SKIPC * sk, 0.f);
            }
            Xs[r][kk] = v;
        }
        __syncthreads();
#pragma unroll
        for (int kk = 0; kk < 64; kk += 4) {
            float4 xv[4];
#pragma unroll
            for (int i = 0; i < 4; i++)
                xv[i] = *(const float4*)&Xs[ty + 8 * i][kk];
#pragma unroll
            for (int j = 0; j < 2; j++) {
                int c = tx + 32 * j;
                if (c < 40) {
                    float4 wv = *(const float4*)&Ws[c][kk];
#pragma unroll
                    for (int i = 0; i < 4; i++) {
                        acc[i][j] += xv[i].x * wv.x + xv[i].y * wv.y +
                                     xv[i].z * wv.z + xv[i].w * wv.w;
                    }
                }
            }
        }
        __syncthreads();
    }
    float as0 = a_s[tx],                 ad0 = a_d[tx];
    float as1 = (tx < 8) ? a_s[32 + tx] : 0.f;
    float ad1 = (tx < 8) ? a_d[32 + tx] : 0.f;
#pragma unroll
    for (int i = 0; i < 4; i++) {
        int row = row0 + ty + 8 * i;
        if (row < nrows) {
            Y[row * 40 + tx] = acc[i][0];
            if (tx < 8) Y[row * 40 + 32 + tx] = acc[i][1];
            float ss = acc[i][0] * as0 + acc[i][1] * as1;
            float dd = acc[i][0] * ad0 + acc[i][1] * ad1;
#pragma unroll
            for (int o = 16; o; o >>= 1) {
                ss += __shfl_xor_sync(0xffffffffu, ss, o);
                dd += __shfl_xor_sync(0xffffffffu, dd, o);
            }
            if (tx == 0) { g_als[row] = ss; g_ald[row] = dd; }
        }
    }
}

// ------------- softmax aggregation, one warp per dst node, all 4 heads ---------
// Single pass: logits are O(10), so exp without max-subtraction is fp32-safe.
__device__ __forceinline__ float lrelu(float e) { return (e > 0.f) ? e : NEGS * e; }

__global__ void agg4_kernel(const float* __restrict__ h,
                            const float* __restrict__ bias,
                            float* __restrict__ outp, int layer) {
    __shared__ float  s_sum[128], s_sq[128];
    __shared__ int    s_colb[8][32];
    __shared__ float4 s_exb[8][32];
    int t = threadIdx.x;
    int w = t >> 5;
    int node = blockIdx.x * 8 + w;
    int lane = t & 31;
    if (t < 128) { s_sum[t] = 0.f; s_sq[t] = 0.f; }
    __syncthreads();

    int s0 = g_rowptr[node], s1 = g_rowptr[node + 1];
    float4 adv = *(const float4*)&g_ald[node * 4];

    float d0 = 0.f, d1 = 0.f, d2 = 0.f, d3 = 0.f;
    float a0 = 0.f, a1 = 0.f, a2 = 0.f, a3 = 0.f;
    for (int i0 = s0; i0 < s1; i0 += 32) {
        int i = i0 + lane;
        float e0 = 0.f, e1 = 0.f, e2 = 0.f, e3 = 0.f;
        int s = 0;
        if (i < s1) {
            s = g_col[i];
            float4 al = *(const float4*)&g_als[s * 4];
            e0 = expf(lrelu(al.x + adv.x));
            e1 = expf(lrelu(al.y + adv.y));
            e2 = expf(lrelu(al.z + adv.z));
            e3 = expf(lrelu(al.w + adv.w));
        }
        d0 += e0; d1 += e1; d2 += e2; d3 += e3;
        s_colb[w][lane] = s;
        s_exb[w][lane]  = make_float4(e0, e1, e2, e3);
        __syncwarp();
        int cnt = min(32, s1 - i0);
#pragma unroll 4
        for (int j = 0; j < cnt; j++) {
            int    sj = s_colb[w][j];
            float4 ex = s_exb[w][j];
            const float* hp = h + sj * 128;
            a0 = fmaf(ex.x, hp[lane],      a0);
            a1 = fmaf(ex.y, hp[32 + lane], a1);
            a2 = fmaf(ex.z, hp[64 + lane], a2);
            a3 = fmaf(ex.w, hp[96 + lane], a3);
        }
        __syncwarp();
    }
#pragma unroll
    for (int o = 16; o; o >>= 1) {
        d0 += __shfl_xor_sync(0xffffffffu, d0, o);
        d1 += __shfl_xor_sync(0xffffffffu, d1, o);
        d2 += __shfl_xor_sync(0xffffffffu, d2, o);
        d3 += __shfl_xor_sync(0xffffffffu, d3, o);
    }
    float v0 = a0 / d0 + bias[lane];
    float v1 = a1 / d1 + bias[32 + lane];
    float v2 = a2 / d2 + bias[64 + lane];
    float v3 = a3 / d3 + bias[96 + lane];
    float* op = outp + node * 128;
    op[lane]      = v0;
    op[32 + lane] = v1;
    op[64 + lane] = v2;
    op[96 + lane] = v3;

    atomicAdd(&s_sum[lane],      v0); atomicAdd(&s_sq[lane],      v0 * v0);
    atomicAdd(&s_sum[32 + lane], v1); atomicAdd(&s_sq[32 + lane], v1 * v1);
    atomicAdd(&s_sum[64 + lane], v2); atomicAdd(&s_sq[64 + lane], v2 * v2);
    atomicAdd(&s_sum[96 + lane], v3); atomicAdd(&s_sq[96 + lane], v3 * v3);
    __syncthreads();
    if (t < 128) {
        int slot = (layer * BNSLOTS + (blockIdx.x & (BNSLOTS - 1))) * HC + t;
        atomicAdd(&g_bnpsum[slot], s_sum[t]);
        atomicAdd(&g_bnpsq[slot],  s_sq[t]);
    }
}

// ---------------- output-layer aggregation (1 head, 40 ch), single pass --------
__global__ void agg1_kernel(const float* __restrict__ h,
                            const float* __restrict__ bias,
                            float* __restrict__ outp) {
    __shared__ int   s_colb[8][32];
    __shared__ float s_exb[8][32];
    int t = threadIdx.x;
    int w = t >> 5;
    int node = blockIdx.x * 8 + w;
    int lane = t & 31;
    if (node >= NN) return;
    int s0 = g_rowptr[node], s1 = g_rowptr[node + 1];
    float adv = g_ald[node];

    float denom = 0.f, acc0 = 0.f, acc1 = 0.f;
    for (int i0 = s0; i0 < s1; i0 += 32) {
        int i = i0 + lane;
        float ex = 0.f;
        int s = 0;
        if (i < s1) {
            s = g_col[i];
            ex = expf(lrelu(g_als[s] + adv));
        }
        denom += ex;
        s_colb[w][lane] = s;
        s_exb[w][lane]  = ex;
        __syncwarp();
        int cnt = min(32, s1 - i0);
#pragma unroll 4
        for (int j = 0; j < cnt; j++) {
            int   sj  = s_colb[w][j];
            float exj = s_exb[w][j];
            const float* hp = h + sj * 40;
            acc0 += exj * hp[lane];
            if (lane < 8) acc1 += exj * hp[32 + lane];
        }
        __syncwarp();
    }
#pragma unroll
    for (int o = 16; o; o >>= 1) denom += __shfl_xor_sync(0xffffffffu, denom, o);
    float inv = 1.f / denom;
    outp[node * 40 + lane] = acc0 * inv + bias[lane];
    if (lane < 8) outp[node * 40 + 32 + lane] = acc1 * inv + bias[32 + lane];
}

// ---------------- batchnorm finalize (reduce 32 slots) ----------------
__global__ void bn_fin_kernel(const float* __restrict__ g,
                              const float* __restrict__ be, int layer) {
    int c = threadIdx.x;
    if (c < 128) {
        float s = 0.f, q = 0.f;
        for (int k = 0; k < BNSLOTS; k++) {
            s += g_bnpsum[(layer * BNSLOTS + k) * HC + c];
            q += g_bnpsq[(layer * BNSLOTS + k) * HC + c];
        }
        float mu  = s * (1.f / NN);
        float var = q * (1.f / NN) - mu * mu;
        float sc  = g[c] * rsqrtf(var + EPSI);
        g_scale[layer * HC + c] = sc;
        g_shift[layer * HC + c] = be[c] - mu * sc;
    }
}

// ---------------- launch ----------------
extern "C" void kernel_launch(void* const* d_in, const int* in_sizes, int n_in,
                              void* d_out, int out_size) {
    const float* x   = (const float*)d_in[0];
    const float* W0  = (const float*)d_in[1];
    const float* as0 = (const float*)d_in[2];
    const float* ad0 = (const float*)d_in[3];
    const float* b0  = (const float*)d_in[4];
    const float* g0  = (const float*)d_in[5];
    const float* be0 = (const float*)d_in[6];
    const float* W1  = (const float*)d_in[7];
    const float* as1 = (const float*)d_in[8];
    const float* ad1 = (const float*)d_in[9];
    const float* b1  = (const float*)d_in[10];
    const float* g1  = (const float*)d_in[11];
    const float* be1 = (const float*)d_in[12];
    const float* W2  = (const float*)d_in[13];
    const float* as2 = (const float*)d_in[14];
    const float* ad2 = (const float*)d_in[15];
    const float* b2  = (const float*)d_in[16];
    const int* ei32  = (const int*)d_in[17];

    float *bufA, *bufB, *bufC;
    cudaGetSymbolAddress((void**)&bufA, g_bufA);
    cudaGetSymbolAddress((void**)&bufB, g_bufB);
    cudaGetSymbolAddress((void**)&bufC, g_bufC);
    float* out = (float*)d_out;

    // CSR build, gemm0 kept as 4th launch (ncu-profiled: verify FFMA2)
    detect_kernel<<<1, 256>>>(ei32);
    init_kernel<<<(NN + 255) / 256, 256>>>();
    hist_kernel<<<(EE + 255) / 256, 256>>>(ei32);
    gemm128_kernel<0><<<(NN + 63) / 64, 256>>>(x, W0, bufA, as0, ad0, NN);
    scanA_kernel<<<SCAN_BLOCKS, 256>>>();
    scanB_kernel<<<1, 256>>>();
    scanC_kernel<<<SCAN_BLOCKS, 256>>>();
    selfloop_kernel<<<(NN + 255) / 256, 256>>>();
    scatter_kernel<<<(EE + 255) / 256, 256>>>(ei32);

    // ---- layer 0 aggregation (BN stats fused) ----
    agg4_kernel<<<NN / 8, 256>>>(bufA, b0, bufB, 0);
    bn_fin_kernel<<<1, 128>>>(g0, be0, 0);

    // ---- layer 1 (relu(bn0(x)) fused into GEMM load) ----
    gemm128_kernel<1><<<(NN + 63) / 64, 256>>>(bufB, W1, bufA, as1, ad1, NN);
    agg4_kernel<<<NN / 8, 256>>>(bufA, b1, bufC, 1);
    bn_fin_kernel<<<1, 128>>>(g1, be1, 1);

    // ---- layer 2 (bn1 + skip recomputed from bufB, fused into GEMM load) ----
    gemm40_kernel<<<(NN + 31) / 32, 256>>>(bufC, W2, bufA, as2, ad2, bufB, NN);
    agg1_kernel<<<(NN + 7) / 8, 256>>>(bufA, b2, out);
}